// round 4
// baseline (speedup 1.0000x reference)
#include <cuda_runtime.h>
#include <cuda_bf16.h>
#include <cstdint>

// out[s,b,d] = x[s,b,0]*W_xy[d,0] + x[s,b,1]*W_xy[d,1]
//            + x[s,b,2]*W_seg[d] + b_xy[d] + b_seg[d] + pe[s,d]
//
// S=256, B=256, D=1024 fp32 -> 268 MB output, store-bandwidth bound.
//
// R4: store through the TMA bulk engine instead of per-thread STG.
//  - grid = 152*4 = 608, one wave; each block owns a CONTIGUOUS run of
//    107-108 rows (432 KB contiguous gmem span).
//  - double-buffered SMEM staging: compute 4 rows (16 KB) -> STS, then one
//    thread issues cp.async.bulk.global.shared::cta (async-proxy bulk copy).
//  - per-thread STG path (the suspected 4.6 TB/s limiter) is bypassed.

#define S_DIM 256
#define B_DIM 256
#define D_DIM 1024
#define NSM     152
#define OCC     4
#define GRID_N  (NSM * OCC)                 // 608
#define ROWS    (S_DIM * B_DIM)             // 65536
#define BASE_R  (ROWS / GRID_N)             // 107
#define REM_R   (ROWS - BASE_R * GRID_N)    // 480
#define MAX_RUN (BASE_R + 1)                // 108
#define RB      4                           // rows per buffer
#define BUF_FLT (RB * D_DIM)                // 4096 floats = 16 KB

__device__ __forceinline__ uint32_t smem_u32(const void* p) {
    uint32_t a;
    asm("{ .reg .u64 t; cvta.to.shared.u64 t, %1; cvt.u32.u64 %0, t; }"
        : "=r"(a) : "l"(p));
    return a;
}

__global__ __launch_bounds__(256, OCC)
void pe_fused_kernel(const float* __restrict__ x,
                     const float* __restrict__ Wxy,
                     const float* __restrict__ bxy,
                     const float* __restrict__ Wseg,
                     const float* __restrict__ bseg,
                     const float* __restrict__ pe,
                     float* __restrict__ out)
{
    __shared__ __align__(128) float buf[2][BUF_FLT];     // 32 KB
    __shared__ float xs[MAX_RUN * 3 + 4];                // <= 328 floats

    const int k     = blockIdx.x;
    const int extra = (k < REM_R) ? k : REM_R;
    const int start = k * BASE_R + extra;                // first global row
    const int count = BASE_R + (k < REM_R ? 1 : 0);      // 107 or 108

    // Stage x for the whole run (contiguous floats).
    const int nflt = count * 3;
    for (int i = threadIdx.x; i < nflt; i += 256)
        xs[i] = x[(size_t)start * 3 + i];

    const int d = threadIdx.x << 2;          // this thread's float4 slice of D

    // Block-lifetime per-d coefficients.
    const float4 w01 = *reinterpret_cast<const float4*>(Wxy + d * 2);
    const float4 w23 = *reinterpret_cast<const float4*>(Wxy + d * 2 + 4);
    const float4 c2  = *reinterpret_cast<const float4*>(Wseg + d);
    const float4 ba  = *reinterpret_cast<const float4*>(bxy + d);
    const float4 bs  = *reinterpret_cast<const float4*>(bseg + d);

    const float c0x = w01.x, c1x = w01.y;
    const float c0y = w01.z, c1y = w01.w;
    const float c0z = w23.x, c1z = w23.y;
    const float c0w = w23.z, c1w = w23.w;

    float4 bsum;                             // b_xy + b_seg
    bsum.x = ba.x + bs.x;
    bsum.y = ba.y + bs.y;
    bsum.z = ba.z + bs.z;
    bsum.w = ba.w + bs.w;

    const uint32_t sbuf0 = smem_u32(&buf[0][0]);
    const uint32_t sbuf1 = smem_u32(&buf[1][0]);

    const int niter = (count + RB - 1) / RB;

    for (int it = 0; it < niter; ++it) {
        const int p = it & 1;
        const int r0 = it * RB;                          // row within run
        const int rows_here = min(RB, count - r0);

        // Before overwriting buffer p, ensure its previous bulk copy has
        // finished READING it (allow 1 group in flight = the other buffer).
        if (it >= 2 && threadIdx.x == 0)
            asm volatile("cp.async.bulk.wait_group.read 1;" ::: "memory");
        __syncthreads();

        float* bp = buf[p];
        #pragma unroll
        for (int i = 0; i < RB; ++i) {
            if (i < rows_here) {
                const int rg = start + r0 + i;           // global row
                const int s  = rg >> 8;                  // / B_DIM
                const float4 pp = *reinterpret_cast<const float4*>(
                    pe + (size_t)s * D_DIM + d);
                const float x0 = xs[(r0 + i) * 3 + 0];
                const float x1 = xs[(r0 + i) * 3 + 1];
                const float x2 = xs[(r0 + i) * 3 + 2];
                float4 v;
                v.x = fmaf(x0, c0x, fmaf(x1, c1x, fmaf(x2, c2.x, pp.x + bsum.x)));
                v.y = fmaf(x0, c0y, fmaf(x1, c1y, fmaf(x2, c2.y, pp.y + bsum.y)));
                v.z = fmaf(x0, c0z, fmaf(x1, c1z, fmaf(x2, c2.z, pp.z + bsum.z)));
                v.w = fmaf(x0, c0w, fmaf(x1, c1w, fmaf(x2, c2.w, pp.w + bsum.w)));
                *reinterpret_cast<float4*>(bp + i * D_DIM + d) = v;
            }
        }
        __syncthreads();

        if (threadIdx.x == 0) {
            // Make generic-proxy STS visible to the async proxy, then issue
            // one bulk copy for the whole buffer (contiguous gmem span).
            asm volatile("fence.proxy.async.shared::cta;" ::: "memory");
            float* gdst = out + (size_t)(start + r0) * D_DIM;
            const uint32_t saddr = p ? sbuf1 : sbuf0;
            const uint32_t bytes = (uint32_t)rows_here * D_DIM * 4u;
            asm volatile(
                "cp.async.bulk.global.shared::cta.bulk_group [%0], [%1], %2;"
                :: "l"(gdst), "r"(saddr), "r"(bytes) : "memory");
            asm volatile("cp.async.bulk.commit_group;" ::: "memory");
        }
    }

    // Drain all outstanding bulk groups before exit.
    if (threadIdx.x == 0)
        asm volatile("cp.async.bulk.wait_group 0;" ::: "memory");
}

extern "C" void kernel_launch(void* const* d_in, const int* in_sizes, int n_in,
                              void* d_out, int out_size)
{
    const float* x    = (const float*)d_in[0];   // [S,B,3]
    const float* Wxy  = (const float*)d_in[1];   // [D,2]
    const float* bxy  = (const float*)d_in[2];   // [D]
    const float* Wseg = (const float*)d_in[3];   // [D,1]
    const float* bseg = (const float*)d_in[4];   // [D]
    const float* pe   = (const float*)d_in[5];   // [MAX_LEN,1,D]
    float* out = (float*)d_out;                  // [S,B,D]

    pe_fused_kernel<<<GRID_N, 256>>>(x, Wxy, bxy, Wseg, bseg, pe, out);
}